// round 3
// baseline (speedup 1.0000x reference)
#include <cuda_runtime.h>
#include <cuda_bf16.h>
#include <math.h>

#define NB   16
#define XW   1022
#define NP   512
#define HH   256
#define SEG  516        // per-warp smem FFT segment stride (float2), decorrelates banks

// Scratch (device globals -- allocation-free)
static __device__ float2 g_F1[(size_t)NB * HH * NP];          // F1 transposed: [b][k][r], 16.8 MB
static __device__ float  g_planes[(size_t)4 * NB * HH * HH];  // 16.8 MB
static __device__ float  g_v[(size_t)NB * HH * HH];           // 4.2 MB
static __device__ float2 g_tw[256];

// ---------------------------------------------------------------------------
__global__ void k_twiddle() {
    int k = threadIdx.x;
    float s, c;
    sincospif(-(float)k / 256.0f, &s, &c);
    g_tw[k] = make_float2(c, s);
}

__device__ __forceinline__ float2 cadd(float2 a, float2 b) { return make_float2(a.x + b.x, a.y + b.y); }
__device__ __forceinline__ float2 csub(float2 a, float2 b) { return make_float2(a.x - b.x, a.y - b.y); }
__device__ __forceinline__ float2 cmul(float2 a, float2 b) {
    return make_float2(a.x * b.x - a.y * b.y, a.x * b.y + a.y * b.x);
}

// Warp-private 512-pt radix-2 DIT FFT over s[0..511] (bit-reversed input),
// only __syncwarp between stages (no block barriers).
__device__ __forceinline__ void fft512_warp(float2* s, int l) {
#pragma unroll
    for (int st = 0; st < 9; st++) {
        int half = 1 << st;
#pragma unroll
        for (int m = 0; m < 8; m++) {
            int q   = l + 32 * m;            // butterfly id 0..255
            int pos = q & (half - 1);
            int i0  = ((q >> st) << (st + 1)) | pos;
            int i1  = i0 + half;
            float2 w = g_tw[pos << (8 - st)];
            float2 u = s[i0], v = s[i1];
            float2 wv = cmul(w, v);
            s[i0] = cadd(u, wv);
            s[i1] = csub(u, wv);
        }
        __syncwarp();
    }
}

// ---------------------------------------------------------------------------
// Kernel 1: fused spd(1x1 conv + BN + SiLU) + row real-FFT (2 rows packed per
// complex FFT, one FFT per warp). Writes F1 transposed [b][k][r] via a
// block-level smem transpose (128B chunks).
__global__ void k_rowfft(const float* __restrict__ x,
                         const float* __restrict__ w4,
                         const float* __restrict__ bng,
                         const float* __restrict__ bnb) {
    __shared__ float2 s[6144];     // 48KB: FFT phase uses 8*SEG=4128, transpose phase 256*17=4352
    int t = threadIdx.x;           // 256
    int w = t >> 5, l = t & 31;
    int bx = blockIdx.x;           // 0..31
    int b  = blockIdx.y;
    int rp = bx * 8 + w;           // row pair 0..255 (rows 2rp, 2rp+1 of y)

    float w0 = w4[0], w1 = w4[1], w2 = w4[2], w3 = w4[3];
    float sc = bng[0] * rsqrtf(1.0f + 1e-5f);
    float bi = bnb[0];

    const float* xr0 = x + (size_t)b * XW * XW + (size_t)(4 * rp) * XW;
    float2* sw = s + w * SEG;
    bool row1ok = (rp < 255);      // y row 2rp+1 exists except rp==255 (row 511 is pad)

#pragma unroll
    for (int m = 0; m < 16; m++) {
        int j = l + 32 * m;
        float y0 = 0.0f, y1 = 0.0f;
        if (j < 511) {
            float2 a = *(const float2*)(xr0 + 2 * j);
            float2 c = *(const float2*)(xr0 + XW + 2 * j);
            float z = w0 * a.x + w1 * c.x + w2 * a.y + w3 * c.y;
            z = sc * z + bi;
            y0 = z / (1.0f + expf(-z));
            if (row1ok) {
                float2 a2 = *(const float2*)(xr0 + 2 * (size_t)XW + 2 * j);
                float2 c2 = *(const float2*)(xr0 + 3 * (size_t)XW + 2 * j);
                float z2 = w0 * a2.x + w1 * c2.x + w2 * a2.y + w3 * c2.y;
                z2 = sc * z2 + bi;
                y1 = z2 / (1.0f + expf(-z2));
            }
        }
        sw[__brev(j) >> 23] = make_float2(y0, y1);
    }
    __syncwarp();

    fft512_warp(sw, l);

    // Unpack both real spectra into registers (k = 0..255)
    float2 E[8], O[8];
#pragma unroll
    for (int m = 0; m < 8; m++) {
        int k = l + 32 * m;
        float2 Fk = sw[k];
        float2 Fn = sw[(NP - k) & (NP - 1)];
        E[m] = make_float2(0.5f * (Fk.x + Fn.x), 0.5f * (Fk.y - Fn.y));  // row 2rp
        float2 D = make_float2(0.5f * (Fk.x - Fn.x), 0.5f * (Fk.y + Fn.y));
        O[m] = make_float2(D.y, -D.x);                                   // row 2rp+1
    }
    __syncthreads();   // all warps done reading s -> safe to reuse as transpose buffer

    // Transpose staging: sT[k][rr], rr = local row (0..15), stride 17 (conflict-free)
#pragma unroll
    for (int m = 0; m < 8; m++) {
        int k = l + 32 * m;
        s[k * 17 + 2 * w]     = E[m];
        s[k * 17 + 2 * w + 1] = O[m];
    }
    __syncthreads();

    // Coalesced write: F1T[b][k][16*bx + rr], 128B per 16 threads
    float2* F1b = g_F1 + (size_t)b * HH * NP + 16 * bx;
#pragma unroll
    for (int it = 0; it < 16; it++) {
        int i  = t + 256 * it;     // 4096 entries
        int k  = i >> 4, rr = i & 15;
        F1b[(size_t)k * NP + rr] = s[k * 17 + rr];
    }
}

// ---------------------------------------------------------------------------
// Kernel 2: column FFT, one column per warp (coalesced 4KB column reads from
// F1T), then block-cooperative split-write into the 4 planes (32B chunks).
__global__ void k_colfft() {
    __shared__ float2 s[8 * SEG];  // 33KB
    int t = threadIdx.x;           // 256
    int w = t >> 5, l = t & 31;
    int bx = blockIdx.x;           // 0..31
    int b  = blockIdx.y;
    int k  = bx * 8 + w;

    const float2* col = g_F1 + ((size_t)b * HH + k) * NP;
    float2* sw = s + w * SEG;
#pragma unroll
    for (int m = 0; m < 16; m++) {
        int j = l + 32 * m;
        sw[__brev(j) >> 23] = col[j];
    }
    __syncwarp();

    fft512_warp(sw, l);
    __syncthreads();

    const size_t ps = (size_t)NB * HH * HH;
    int k0 = bx * 8;
#pragma unroll
    for (int it = 0; it < 16; it++) {
        int i = t + 256 * it;      // 4096 = 512 n x 8 c
        int n = i >> 3, c = i & 7;
        float2 v = s[c * SEG + n];
        int kk = k0 + c;
        if (n < HH) {
            size_t o = ((size_t)b * HH + n) * HH + kk;
            g_planes[o]      = v.x;    // low.real
            g_planes[ps + o] = v.y;    // low.imag
        } else {
            size_t o = ((size_t)b * HH + (n - HH)) * HH + kk;
            g_planes[2 * ps + o] = v.x;  // high.real
            g_planes[3 * ps + o] = v.y;  // high.imag
        }
    }
}

// ---------------------------------------------------------------------------
// Kernel 3: per-plane 3x3 conv + bias, cumprod over batch, 1x1 fuse,
// BN+SiLU, BN+ReLU -> v (16,256,256)
__global__ void k_cumprod(const float* __restrict__ sw9, const float* __restrict__ sb,
                          const float* __restrict__ fw,  const float* __restrict__ fg,
                          const float* __restrict__ fb,  const float* __restrict__ gg,
                          const float* __restrict__ gb) {
    __shared__ float s_w[9];
    int t = threadIdx.x;           // 256
    if (t < 9) s_w[t] = sw9[t];
    __syncthreads();

    int i = blockIdx.x;            // row
    int j = t;                     // col

    float sdib = sb[0];
    float fsc  = fg[0] * rsqrtf(1.0f + 1e-5f);
    float fbi  = fb[0];
    float gsc  = gg[0] * rsqrtf(1.0f + 1e-5f);
    float gbi  = gb[0];
    float fwv[4] = {fw[0], fw[1], fw[2], fw[3]};

    float pr[4] = {1.0f, 1.0f, 1.0f, 1.0f};
    const size_t ps = (size_t)NB * HH * HH;

    for (int b = 0; b < NB; b++) {
        float acc = 0.0f;
#pragma unroll
        for (int p = 0; p < 4; p++) {
            const float* Pb = g_planes + (size_t)p * ps + (size_t)b * HH * HH;
            float c = sdib;
#pragma unroll
            for (int dr = 0; dr < 3; dr++) {
                int ri = i + dr - 1;
                if ((unsigned)ri < (unsigned)HH) {
                    const float* row = Pb + (size_t)ri * HH;
#pragma unroll
                    for (int dc = 0; dc < 3; dc++) {
                        int cj = j + dc - 1;
                        float q = ((unsigned)cj < (unsigned)HH) ? __ldg(row + cj) : 0.0f;
                        c = fmaf(s_w[dr * 3 + dc], q, c);
                    }
                }
            }
            pr[p] *= c;
            acc = fmaf(fwv[p], pr[p], acc);
        }
        float u = fsc * acc + fbi;
        u = u / (1.0f + expf(-u));
        float v = fmaxf(gsc * u + gbi, 0.0f);
        g_v[((size_t)b * HH + i) * HH + j] = v;
    }
}

// ---------------------------------------------------------------------------
// Kernel 4: broadcast by w_final into out (16,64,256,256). Pure write stream,
// float4 stores, 1024 blocks x 256 threads.
__global__ void k_bcast(const float* __restrict__ wf, float* __restrict__ out) {
    __shared__ float swf[64];
    int t = threadIdx.x;           // 256
    if (t < 64) swf[t] = wf[t];
    __syncthreads();

    int b  = blockIdx.y;
    int r  = blockIdx.x * 4 + (t >> 6);    // 4 rows per block
    int c4 = (t & 63);                      // float4 lane within row

    float4 v4 = *(const float4*)(g_v + ((size_t)b * HH + r) * HH + 4 * c4);
    float* ob = out + ((size_t)b * 64 * HH + r) * HH + 4 * c4;
#pragma unroll
    for (int o = 0; o < 64; o++) {
        float wv = swf[o];
        *(float4*)(ob + (size_t)o * HH * HH) = make_float4(wv * v4.x, wv * v4.y, wv * v4.z, wv * v4.w);
    }
}

// ---------------------------------------------------------------------------
extern "C" void kernel_launch(void* const* d_in, const int* in_sizes, int n_in,
                              void* d_out, int out_size) {
    const float* x       = (const float*)d_in[0];
    // gw branch (indices 1..8) is dead: softmax over the singleton K*K axis == 1.
    const float* w_spd   = (const float*)d_in[9];
    const float* bn_g    = (const float*)d_in[10];
    const float* bn_b    = (const float*)d_in[11];
    const float* sdi_w   = (const float*)d_in[12];
    const float* sdi_b   = (const float*)d_in[13];
    const float* fuse_w  = (const float*)d_in[14];
    const float* fuse_g  = (const float*)d_in[15];
    const float* fuse_b  = (const float*)d_in[16];
    const float* gen_g   = (const float*)d_in[17];
    const float* gen_b   = (const float*)d_in[18];
    const float* w_final = (const float*)d_in[19];
    float* out = (float*)d_out;

    k_twiddle<<<1, 256>>>();

    dim3 g1(32, NB);
    k_rowfft<<<g1, 256>>>(x, w_spd, bn_g, bn_b);

    dim3 g2(32, NB);
    k_colfft<<<g2, 256>>>();

    k_cumprod<<<HH, 256>>>(sdi_w, sdi_b, fuse_w, fuse_g, fuse_b, gen_g, gen_b);

    dim3 g4(64, NB);
    k_bcast<<<g4, 256>>>(w_final, out);
}

// round 4
// speedup vs baseline: 1.1957x; 1.1957x over previous
#include <cuda_runtime.h>
#include <cuda_bf16.h>
#include <math.h>

#define NB   16
#define XW   1022
#define NP   512
#define HH   256
#define SEG  516        // per-warp smem FFT segment stride (float2)

// Scratch (device globals -- allocation-free)
static __device__ float2 g_F1[(size_t)NB * HH * NP];          // row-FFT, transposed [b][k][r]
static __device__ float  g_planes[(size_t)4 * NB * HH * HH];  // 4 fourier planes
static __device__ float  g_cp[(size_t)4 * NB * HH * HH];      // per-plane cumprod

__device__ __forceinline__ float2 cadd(float2 a, float2 b) { return make_float2(a.x + b.x, a.y + b.y); }
__device__ __forceinline__ float2 csub(float2 a, float2 b) { return make_float2(a.x - b.x, a.y - b.y); }
__device__ __forceinline__ float2 cmul(float2 a, float2 b) {
    return make_float2(a.x * b.x - a.y * b.y, a.x * b.y + a.y * b.x);
}

// Warp-private 512-pt radix-2 DIT FFT (bit-reversed input), __syncwarp only.
__device__ __forceinline__ void fft512_warp(float2* s, const float2* tw, int l) {
#pragma unroll
    for (int st = 0; st < 9; st++) {
        int half = 1 << st;
#pragma unroll
        for (int m = 0; m < 8; m++) {
            int q   = l + 32 * m;
            int pos = q & (half - 1);
            int i0  = ((q >> st) << (st + 1)) | pos;
            int i1  = i0 + half;
            float2 w = tw[pos << (8 - st)];
            float2 u = s[i0], v = s[i1];
            float2 wv = cmul(w, v);
            s[i0] = cadd(u, wv);
            s[i1] = csub(u, wv);
        }
        __syncwarp();
    }
}

// ---------------------------------------------------------------------------
// Kernel 1: fused spd(1x1 conv + BN + SiLU) + row real-FFT (2 rows per complex
// FFT, one FFT per warp). Writes F1 transposed [b][k][r].
__global__ void k_rowfft(const float* __restrict__ x,
                         const float* __restrict__ w4,
                         const float* __restrict__ bng,
                         const float* __restrict__ bnb) {
    __shared__ float2 s[6144];     // FFT phase: 8*SEG=4128; transpose phase: 256*17=4352
    __shared__ float2 s_tw[256];
    int t = threadIdx.x;           // 256
    int w = t >> 5, l = t & 31;
    int bx = blockIdx.x;           // 0..31
    int b  = blockIdx.y;
    int rp = bx * 8 + w;           // row pair (rows 2rp, 2rp+1 of y)

    { float sn, cs; sincospif(-(float)t / 256.0f, &sn, &cs); s_tw[t] = make_float2(cs, sn); }

    float w0 = w4[0], w1 = w4[1], w2 = w4[2], w3 = w4[3];
    float sc = bng[0] * rsqrtf(1.0f + 1e-5f);
    float bi = bnb[0];

    const float* xr0 = x + (size_t)b * XW * XW + (size_t)(4 * rp) * XW;
    float2* sw = s + w * SEG;
    bool row1ok = (rp < 255);

#pragma unroll
    for (int m = 0; m < 16; m++) {
        int j = l + 32 * m;
        float y0 = 0.0f, y1 = 0.0f;
        if (j < 511) {
            float2 a = *(const float2*)(xr0 + 2 * j);
            float2 c = *(const float2*)(xr0 + XW + 2 * j);
            float z = w0 * a.x + w1 * c.x + w2 * a.y + w3 * c.y;
            z = sc * z + bi;
            y0 = z / (1.0f + expf(-z));
            if (row1ok) {
                float2 a2 = *(const float2*)(xr0 + 2 * (size_t)XW + 2 * j);
                float2 c2 = *(const float2*)(xr0 + 3 * (size_t)XW + 2 * j);
                float z2 = w0 * a2.x + w1 * c2.x + w2 * a2.y + w3 * c2.y;
                z2 = sc * z2 + bi;
                y1 = z2 / (1.0f + expf(-z2));
            }
        }
        sw[__brev(j) >> 23] = make_float2(y0, y1);
    }
    __syncthreads();               // also covers s_tw visibility

    fft512_warp(sw, s_tw, l);

    float2 E[8], O[8];
#pragma unroll
    for (int m = 0; m < 8; m++) {
        int k = l + 32 * m;
        float2 Fk = sw[k];
        float2 Fn = sw[(NP - k) & (NP - 1)];
        E[m] = make_float2(0.5f * (Fk.x + Fn.x), 0.5f * (Fk.y - Fn.y));
        float2 D = make_float2(0.5f * (Fk.x - Fn.x), 0.5f * (Fk.y + Fn.y));
        O[m] = make_float2(D.y, -D.x);
    }
    __syncthreads();

#pragma unroll
    for (int m = 0; m < 8; m++) {
        int k = l + 32 * m;
        s[k * 17 + 2 * w]     = E[m];
        s[k * 17 + 2 * w + 1] = O[m];
    }
    __syncthreads();

    float2* F1b = g_F1 + (size_t)b * HH * NP + 16 * bx;
#pragma unroll
    for (int it = 0; it < 16; it++) {
        int i  = t + 256 * it;
        int k  = i >> 4, rr = i & 15;
        F1b[(size_t)k * NP + rr] = s[k * 17 + rr];
    }
}

// ---------------------------------------------------------------------------
// Kernel 2: column FFT (one column per warp, coalesced 4KB column reads),
// split-write into the 4 planes.
__global__ void k_colfft() {
    __shared__ float2 s[8 * SEG];
    __shared__ float2 s_tw[256];
    int t = threadIdx.x;           // 256
    int w = t >> 5, l = t & 31;
    int bx = blockIdx.x;           // 0..31
    int b  = blockIdx.y;
    int k  = bx * 8 + w;

    { float sn, cs; sincospif(-(float)t / 256.0f, &sn, &cs); s_tw[t] = make_float2(cs, sn); }
    __syncthreads();

    const float2* col = g_F1 + ((size_t)b * HH + k) * NP;
    float2* sw = s + w * SEG;
#pragma unroll
    for (int m = 0; m < 16; m++) {
        int j = l + 32 * m;
        sw[__brev(j) >> 23] = col[j];
    }
    __syncwarp();

    fft512_warp(sw, s_tw, l);
    __syncthreads();

    const size_t ps = (size_t)NB * HH * HH;
    int k0 = bx * 8;
#pragma unroll
    for (int it = 0; it < 16; it++) {
        int i = t + 256 * it;
        int n = i >> 3, c = i & 7;
        float2 v = s[c * SEG + n];
        int kk = k0 + c;
        if (n < HH) {
            size_t o = ((size_t)b * HH + n) * HH + kk;
            g_planes[o]      = v.x;
            g_planes[ps + o] = v.y;
        } else {
            size_t o = ((size_t)b * HH + (n - HH)) * HH + kk;
            g_planes[2 * ps + o] = v.x;
            g_planes[3 * ps + o] = v.y;
        }
    }
}

// ---------------------------------------------------------------------------
// Kernel 3: per-(plane,pixel) 3x3 conv + bias and cumprod over batch in a
// register. One thread per (plane, pixel): 4x the warps of the fused version.
__global__ void k_sdi(const float* __restrict__ sw9, const float* __restrict__ sb) {
    __shared__ float s_w[9];
    int t = threadIdx.x;           // 256
    if (t < 9) s_w[t] = sw9[t];
    __syncthreads();

    int p = blockIdx.y;            // plane
    int i = blockIdx.x;            // row
    int j = t;                     // col
    float sdib = sb[0];

    const size_t ps = (size_t)NB * HH * HH;
    const float* P = g_planes + (size_t)p * ps;
    float* C = g_cp + (size_t)p * ps + (size_t)i * HH + j;

    float pr = 1.0f;
    for (int b = 0; b < NB; b++) {
        const float* Pb = P + (size_t)b * HH * HH;
        float c = sdib;
#pragma unroll
        for (int dr = 0; dr < 3; dr++) {
            int ri = i + dr - 1;
            if ((unsigned)ri < (unsigned)HH) {
                const float* row = Pb + (size_t)ri * HH;
#pragma unroll
                for (int dc = 0; dc < 3; dc++) {
                    int cj = j + dc - 1;
                    float q = ((unsigned)cj < (unsigned)HH) ? __ldg(row + cj) : 0.0f;
                    c = fmaf(s_w[dr * 3 + dc], q, c);
                }
            }
        }
        pr *= c;
        C[(size_t)b * HH * HH] = pr;
    }
}

// ---------------------------------------------------------------------------
// Kernel 4: fuse 4 cumprod planes + BN+SiLU + BN+ReLU + broadcast by w_final
// into out (16,64,256,256). float4 stores, write-streaming.
__global__ void k_bcast(const float* __restrict__ fw,  const float* __restrict__ fg,
                        const float* __restrict__ fb,  const float* __restrict__ gg,
                        const float* __restrict__ gb,  const float* __restrict__ wf,
                        float* __restrict__ out) {
    __shared__ float swf[64];
    int t = threadIdx.x;           // 256
    if (t < 64) swf[t] = wf[t];
    __syncthreads();

    int b  = blockIdx.y;
    int r  = blockIdx.x * 4 + (t >> 6);
    int c4 = (t & 63);

    float fsc = fg[0] * rsqrtf(1.0f + 1e-5f);
    float fbi = fb[0];
    float gsc = gg[0] * rsqrtf(1.0f + 1e-5f);
    float gbi = gb[0];
    float fw0 = fw[0], fw1 = fw[1], fw2 = fw[2], fw3 = fw[3];

    const size_t ps = (size_t)NB * HH * HH;
    size_t off = ((size_t)b * HH + r) * HH + 4 * c4;
    float4 a0 = *(const float4*)(g_cp + off);
    float4 a1 = *(const float4*)(g_cp + ps + off);
    float4 a2 = *(const float4*)(g_cp + 2 * ps + off);
    float4 a3 = *(const float4*)(g_cp + 3 * ps + off);

    float v[4];
#pragma unroll
    for (int e = 0; e < 4; e++) {
        float acc = fw0 * ((const float*)&a0)[e]
                  + fw1 * ((const float*)&a1)[e]
                  + fw2 * ((const float*)&a2)[e]
                  + fw3 * ((const float*)&a3)[e];
        float u = fsc * acc + fbi;
        u = u / (1.0f + expf(-u));
        v[e] = fmaxf(gsc * u + gbi, 0.0f);
    }
    float4 v4 = make_float4(v[0], v[1], v[2], v[3]);

    float* ob = out + ((size_t)b * 64 * HH + r) * HH + 4 * c4;
#pragma unroll
    for (int o = 0; o < 64; o++) {
        float wv = swf[o];
        *(float4*)(ob + (size_t)o * HH * HH) = make_float4(wv * v4.x, wv * v4.y, wv * v4.z, wv * v4.w);
    }
}

// ---------------------------------------------------------------------------
extern "C" void kernel_launch(void* const* d_in, const int* in_sizes, int n_in,
                              void* d_out, int out_size) {
    const float* x       = (const float*)d_in[0];
    // gw branch (indices 1..8) is dead: softmax over the singleton K*K axis == 1.
    const float* w_spd   = (const float*)d_in[9];
    const float* bn_g    = (const float*)d_in[10];
    const float* bn_b    = (const float*)d_in[11];
    const float* sdi_w   = (const float*)d_in[12];
    const float* sdi_b   = (const float*)d_in[13];
    const float* fuse_w  = (const float*)d_in[14];
    const float* fuse_g  = (const float*)d_in[15];
    const float* fuse_b  = (const float*)d_in[16];
    const float* gen_g   = (const float*)d_in[17];
    const float* gen_b   = (const float*)d_in[18];
    const float* w_final = (const float*)d_in[19];
    float* out = (float*)d_out;

    dim3 g1(32, NB);
    k_rowfft<<<g1, 256>>>(x, w_spd, bn_g, bn_b);

    dim3 g2(32, NB);
    k_colfft<<<g2, 256>>>();

    dim3 g3(HH, 4);
    k_sdi<<<g3, 256>>>(sdi_w, sdi_b);

    dim3 g4(64, NB);
    k_bcast<<<g4, 256>>>(fuse_w, fuse_g, fuse_b, gen_g, gen_b, w_final, out);
}

// round 7
// speedup vs baseline: 1.3158x; 1.1004x over previous
#include <cuda_runtime.h>
#include <cuda_bf16.h>
#include <math.h>

#define NB   16
#define XW   1022
#define NP   512
#define HH   256
#define SEG  516        // per-warp smem FFT segment stride (float2)

// Scratch (device globals -- allocation-free)
static __device__ float2 g_F1[(size_t)NB * HH * NP];          // row-FFT, transposed [b][k][r]
static __device__ float  g_planes[(size_t)4 * NB * HH * HH];  // 4 fourier planes
static __device__ float  g_cp[(size_t)4 * NB * HH * HH];      // per-plane cumprod

__device__ __forceinline__ float2 cadd(float2 a, float2 b) { return make_float2(a.x + b.x, a.y + b.y); }
__device__ __forceinline__ float2 csub(float2 a, float2 b) { return make_float2(a.x - b.x, a.y - b.y); }
__device__ __forceinline__ float2 cmul(float2 a, float2 b) {
    return make_float2(a.x * b.x - a.y * b.y, a.x * b.y + a.y * b.x);
}

// Bank swizzle (involution): kills the 32-way conflict of the bit-reversed
// scatter (stride-16-complex = 128B = bank period) and leaves contiguous
// access patterns conflict-free.
__device__ __forceinline__ int sphys(int i) { return i ^ ((i >> 4) & 15); }

// Warp-private 512-pt radix-2 DIT FFT over a swizzled segment (bit-reversed
// input at phys positions), __syncwarp only.
__device__ __forceinline__ void fft512_warp(float2* s, const float2* tw, int l) {
#pragma unroll
    for (int st = 0; st < 9; st++) {
        int half = 1 << st;
#pragma unroll
        for (int m = 0; m < 8; m++) {
            int q   = l + 32 * m;
            int pos = q & (half - 1);
            int i0  = ((q >> st) << (st + 1)) | pos;
            int i1  = i0 + half;
            float2 w = tw[pos << (8 - st)];
            float2 u = s[sphys(i0)], v = s[sphys(i1)];
            float2 wv = cmul(w, v);
            s[sphys(i0)] = cadd(u, wv);
            s[sphys(i1)] = csub(u, wv);
        }
        __syncwarp();
    }
}

// ---------------------------------------------------------------------------
// Kernel 1: fused spd(1x1 conv + BN + SiLU) + row real-FFT (2 rows per complex
// FFT, one FFT per warp). Writes F1 transposed [b][k][r].
__global__ void k_rowfft(const float* __restrict__ x,
                         const float* __restrict__ w4,
                         const float* __restrict__ bng,
                         const float* __restrict__ bnb) {
    __shared__ float2 s[4352];     // FFT phase: 8*SEG=4128; transpose phase: 256*17=4352
    __shared__ float2 s_tw[256];
    int t = threadIdx.x;           // 256
    int w = t >> 5, l = t & 31;
    int bx = blockIdx.x;           // 0..31
    int b  = blockIdx.y;
    int rp = bx * 8 + w;           // row pair (rows 2rp, 2rp+1 of y)

    { float sn, cs; sincospif(-(float)t / 256.0f, &sn, &cs); s_tw[t] = make_float2(cs, sn); }

    float w0 = w4[0], w1 = w4[1], w2 = w4[2], w3 = w4[3];
    float sc = bng[0] * rsqrtf(1.0f + 1e-5f);
    float bi = bnb[0];

    const float* xr0 = x + (size_t)b * XW * XW + (size_t)(4 * rp) * XW;
    float2* sw = s + w * SEG;
    bool row1ok = (rp < 255);

#pragma unroll
    for (int m = 0; m < 16; m++) {
        int j = l + 32 * m;
        float y0 = 0.0f, y1 = 0.0f;
        if (j < 511) {
            float2 a = *(const float2*)(xr0 + 2 * j);
            float2 c = *(const float2*)(xr0 + XW + 2 * j);
            float z = w0 * a.x + w1 * c.x + w2 * a.y + w3 * c.y;
            z = sc * z + bi;
            y0 = z / (1.0f + expf(-z));
            if (row1ok) {
                float2 a2 = *(const float2*)(xr0 + 2 * (size_t)XW + 2 * j);
                float2 c2 = *(const float2*)(xr0 + 3 * (size_t)XW + 2 * j);
                float z2 = w0 * a2.x + w1 * c2.x + w2 * a2.y + w3 * c2.y;
                z2 = sc * z2 + bi;
                y1 = z2 / (1.0f + expf(-z2));
            }
        }
        sw[sphys(__brev(j) >> 23)] = make_float2(y0, y1);
    }
    __syncthreads();               // also covers s_tw visibility

    fft512_warp(sw, s_tw, l);

    float2 E[8], O[8];
#pragma unroll
    for (int m = 0; m < 8; m++) {
        int k = l + 32 * m;
        float2 Fk = sw[sphys(k)];
        float2 Fn = sw[sphys((NP - k) & (NP - 1))];
        E[m] = make_float2(0.5f * (Fk.x + Fn.x), 0.5f * (Fk.y - Fn.y));
        float2 D = make_float2(0.5f * (Fk.x - Fn.x), 0.5f * (Fk.y + Fn.y));
        O[m] = make_float2(D.y, -D.x);
    }
    __syncthreads();

#pragma unroll
    for (int m = 0; m < 8; m++) {
        int k = l + 32 * m;
        s[k * 17 + 2 * w]     = E[m];
        s[k * 17 + 2 * w + 1] = O[m];
    }
    __syncthreads();

    float2* F1b = g_F1 + (size_t)b * HH * NP + 16 * bx;
#pragma unroll
    for (int it = 0; it < 16; it++) {
        int i  = t + 256 * it;
        int k  = i >> 4, rr = i & 15;
        F1b[(size_t)k * NP + rr] = s[k * 17 + rr];
    }
}

// ---------------------------------------------------------------------------
// Kernel 2: column FFT (one column per warp, coalesced 4KB column reads),
// split-write into the 4 planes.
__global__ void k_colfft() {
    __shared__ float2 s[8 * SEG];
    __shared__ float2 s_tw[256];
    int t = threadIdx.x;           // 256
    int w = t >> 5, l = t & 31;
    int bx = blockIdx.x;           // 0..31
    int b  = blockIdx.y;
    int k  = bx * 8 + w;

    { float sn, cs; sincospif(-(float)t / 256.0f, &sn, &cs); s_tw[t] = make_float2(cs, sn); }
    __syncthreads();

    const float2* col = g_F1 + ((size_t)b * HH + k) * NP;
    float2* sw = s + w * SEG;
#pragma unroll
    for (int m = 0; m < 16; m++) {
        int j = l + 32 * m;
        sw[sphys(__brev(j) >> 23)] = col[j];
    }
    __syncwarp();

    fft512_warp(sw, s_tw, l);
    __syncthreads();

    const size_t ps = (size_t)NB * HH * HH;
    int k0 = bx * 8;
#pragma unroll
    for (int it = 0; it < 16; it++) {
        int i = t + 256 * it;
        int n = i >> 3, c = i & 7;
        float2 v = s[c * SEG + sphys(n)];
        int kk = k0 + c;
        if (n < HH) {
            size_t o = ((size_t)b * HH + n) * HH + kk;
            g_planes[o]      = v.x;
            g_planes[ps + o] = v.y;
        } else {
            size_t o = ((size_t)b * HH + (n - HH)) * HH + kk;
            g_planes[2 * ps + o] = v.x;
            g_planes[3 * ps + o] = v.y;
        }
    }
}

// ---------------------------------------------------------------------------
// Kernel 3: per-(plane,pixel) 3x3 conv + bias and cumprod over batch in a
// register. One thread per (plane, pixel).
__global__ void k_sdi(const float* __restrict__ sw9, const float* __restrict__ sb) {
    __shared__ float s_w[9];
    int t = threadIdx.x;           // 256
    if (t < 9) s_w[t] = sw9[t];
    __syncthreads();

    int p = blockIdx.y;            // plane
    int i = blockIdx.x;            // row
    int j = t;                     // col
    float sdib = sb[0];

    const size_t ps = (size_t)NB * HH * HH;
    const float* P = g_planes + (size_t)p * ps;
    float* C = g_cp + (size_t)p * ps + (size_t)i * HH + j;

    float pr = 1.0f;
    for (int b = 0; b < NB; b++) {
        const float* Pb = P + (size_t)b * HH * HH;
        float c = sdib;
#pragma unroll
        for (int dr = 0; dr < 3; dr++) {
            int ri = i + dr - 1;
            if ((unsigned)ri < (unsigned)HH) {
                const float* row = Pb + (size_t)ri * HH;
#pragma unroll
                for (int dc = 0; dc < 3; dc++) {
                    int cj = j + dc - 1;
                    float q = ((unsigned)cj < (unsigned)HH) ? __ldg(row + cj) : 0.0f;
                    c = fmaf(s_w[dr * 3 + dc], q, c);
                }
            }
        }
        pr *= c;
        C[(size_t)b * HH * HH] = pr;
    }
}

// ---------------------------------------------------------------------------
// Kernel 4: fuse 4 cumprod planes + BN+SiLU + BN+ReLU + broadcast by w_final
// into out (16,64,256,256). 4096 blocks, o-loop split 4 ways, streaming stores.
__global__ void k_bcast(const float* __restrict__ fw,  const float* __restrict__ fg,
                        const float* __restrict__ fb,  const float* __restrict__ gg,
                        const float* __restrict__ gb,  const float* __restrict__ wf,
                        float* __restrict__ out) {
    __shared__ float swf[64];
    int t = threadIdx.x;           // 256
    if (t < 64) swf[t] = wf[t];
    __syncthreads();

    int b  = blockIdx.y;
    int r  = blockIdx.x;           // row 0..255
    int og = t >> 6;               // o-group 0..3 (16 o's each)
    int c4 = t & 63;               // float4 lane within row

    float fsc = fg[0] * rsqrtf(1.0f + 1e-5f);
    float fbi = fb[0];
    float gsc = gg[0] * rsqrtf(1.0f + 1e-5f);
    float gbi = gb[0];
    float fw0 = fw[0], fw1 = fw[1], fw2 = fw[2], fw3 = fw[3];

    const size_t ps = (size_t)NB * HH * HH;
    size_t off = ((size_t)b * HH + r) * HH + 4 * c4;
    float4 a0 = *(const float4*)(g_cp + off);
    float4 a1 = *(const float4*)(g_cp + ps + off);
    float4 a2 = *(const float4*)(g_cp + 2 * ps + off);
    float4 a3 = *(const float4*)(g_cp + 3 * ps + off);

    float v[4];
#pragma unroll
    for (int e = 0; e < 4; e++) {
        float acc = fw0 * ((const float*)&a0)[e]
                  + fw1 * ((const float*)&a1)[e]
                  + fw2 * ((const float*)&a2)[e]
                  + fw3 * ((const float*)&a3)[e];
        float u = fsc * acc + fbi;
        u = u / (1.0f + expf(-u));
        v[e] = fmaxf(gsc * u + gbi, 0.0f);
    }

    float* ob = out + ((((size_t)b * 64 + og * 16) * HH + r) * HH + 4 * c4);
#pragma unroll
    for (int oo = 0; oo < 16; oo++) {
        float wv = swf[og * 16 + oo];
        __stcs((float4*)(ob + (size_t)oo * HH * HH),
               make_float4(wv * v[0], wv * v[1], wv * v[2], wv * v[3]));
    }
}

// ---------------------------------------------------------------------------
extern "C" void kernel_launch(void* const* d_in, const int* in_sizes, int n_in,
                              void* d_out, int out_size) {
    const float* x       = (const float*)d_in[0];
    // gw branch (indices 1..8) is dead: softmax over the singleton K*K axis == 1.
    const float* w_spd   = (const float*)d_in[9];
    const float* bn_g    = (const float*)d_in[10];
    const float* bn_b    = (const float*)d_in[11];
    const float* sdi_w   = (const float*)d_in[12];
    const float* sdi_b   = (const float*)d_in[13];
    const float* fuse_w  = (const float*)d_in[14];
    const float* fuse_g  = (const float*)d_in[15];
    const float* fuse_b  = (const float*)d_in[16];
    const float* gen_g   = (const float*)d_in[17];
    const float* gen_b   = (const float*)d_in[18];
    const float* w_final = (const float*)d_in[19];
    float* out = (float*)d_out;

    dim3 g1(32, NB);
    k_rowfft<<<g1, 256>>>(x, w_spd, bn_g, bn_b);

    dim3 g2(32, NB);
    k_colfft<<<g2, 256>>>();

    dim3 g3(HH, 4);
    k_sdi<<<g3, 256>>>(sdi_w, sdi_b);

    dim3 g4(HH, NB);
    k_bcast<<<g4, 256>>>(fuse_w, fuse_g, fuse_b, gen_g, gen_b, w_final, out);
}

// round 8
// speedup vs baseline: 1.5492x; 1.1773x over previous
#include <cuda_runtime.h>
#include <cuda_bf16.h>
#include <math.h>

#define NB   16
#define XW   1022
#define NP   512
#define HH   256
#define SEG  516        // per-warp smem FFT segment stride (float2)

// Scratch (device globals -- allocation-free)
static __device__ float2 g_F1[(size_t)NB * HH * NP];          // row-FFT, transposed [b][k][r]
static __device__ float  g_planes[(size_t)4 * NB * HH * HH];  // 4 fourier planes
static __device__ float  g_cp[(size_t)4 * NB * HH * HH];      // per-plane cumprod

__device__ __forceinline__ float2 cadd(float2 a, float2 b) { return make_float2(a.x + b.x, a.y + b.y); }
__device__ __forceinline__ float2 csub(float2 a, float2 b) { return make_float2(a.x - b.x, a.y - b.y); }
__device__ __forceinline__ float2 cmul(float2 a, float2 b) {
    return make_float2(a.x * b.x - a.y * b.y, a.x * b.y + a.y * b.x);
}

// Bank swizzle (involution) for FFT data segments.
__device__ __forceinline__ int sphys(int i) { return i ^ ((i >> 4) & 15); }
// Separate swizzle for the twiddle table (octet access pattern hits strides
// 4/32 which are 8-way conflicted un-swizzled).
__device__ __forceinline__ int twp(int i) { return i ^ ((i >> 4) & 15); }

// Warp-private 512-pt FFT, radix-2 DIT semantics but with THREE stages fused
// per shared-memory pass (radix-8 octets held in registers). Input must be
// bit-reversed (base-2) at sphys positions. 3 smem passes instead of 9.
__device__ __forceinline__ void fft512_warp(float2* s, const float2* tw, int l) {
#pragma unroll
    for (int st = 0; st < 9; st += 3) {
        int h = 1 << st;
#pragma unroll
        for (int m = 0; m < 2; m++) {
            int q   = l + 32 * m;            // octet id 0..63
            int pos = q & (h - 1);
            int base = (q >> st) << (st + 3);
            int i0 = base + pos;

            float2 a0 = s[sphys(i0)];
            float2 a1 = s[sphys(i0 + h)];
            float2 a2 = s[sphys(i0 + 2 * h)];
            float2 a3 = s[sphys(i0 + 3 * h)];
            float2 a4 = s[sphys(i0 + 4 * h)];
            float2 a5 = s[sphys(i0 + 5 * h)];
            float2 a6 = s[sphys(i0 + 6 * h)];
            float2 a7 = s[sphys(i0 + 7 * h)];

            // stage st (all four pairs share one twiddle)
            float2 w1 = tw[twp(pos << (8 - st))];
            float2 t;
            t = cmul(w1, a1); float2 b0 = cadd(a0, t), b1 = csub(a0, t);
            t = cmul(w1, a3); float2 b2 = cadd(a2, t), b3 = csub(a2, t);
            t = cmul(w1, a5); float2 b4 = cadd(a4, t), b5 = csub(a4, t);
            t = cmul(w1, a7); float2 b6 = cadd(a6, t), b7 = csub(a6, t);

            // stage st+1
            float2 w2a = tw[twp(pos << (7 - st))];
            float2 w2b = tw[twp((pos + h) << (7 - st))];
            t = cmul(w2a, b2); float2 c0 = cadd(b0, t), c2 = csub(b0, t);
            t = cmul(w2b, b3); float2 c1 = cadd(b1, t), c3 = csub(b1, t);
            t = cmul(w2a, b6); float2 c4 = cadd(b4, t), c6 = csub(b4, t);
            t = cmul(w2b, b7); float2 c5 = cadd(b5, t), c7 = csub(b5, t);

            // stage st+2
            float2 w30 = tw[twp((pos          ) << (6 - st))];
            float2 w31 = tw[twp((pos +     h) << (6 - st))];
            float2 w32 = tw[twp((pos + 2 * h) << (6 - st))];
            float2 w33 = tw[twp((pos + 3 * h) << (6 - st))];
            t = cmul(w30, c4); float2 d0 = cadd(c0, t), d4 = csub(c0, t);
            t = cmul(w31, c5); float2 d1 = cadd(c1, t), d5 = csub(c1, t);
            t = cmul(w32, c6); float2 d2 = cadd(c2, t), d6 = csub(c2, t);
            t = cmul(w33, c7); float2 d3 = cadd(c3, t), d7 = csub(c3, t);

            s[sphys(i0)]         = d0;
            s[sphys(i0 + h)]     = d1;
            s[sphys(i0 + 2 * h)] = d2;
            s[sphys(i0 + 3 * h)] = d3;
            s[sphys(i0 + 4 * h)] = d4;
            s[sphys(i0 + 5 * h)] = d5;
            s[sphys(i0 + 6 * h)] = d6;
            s[sphys(i0 + 7 * h)] = d7;
        }
        __syncwarp();
    }
}

// ---------------------------------------------------------------------------
// Kernel 1: fused spd(1x1 conv + BN + SiLU) + row real-FFT (2 rows per complex
// FFT, one FFT per warp). Writes F1 transposed [b][k][r].
__global__ void k_rowfft(const float* __restrict__ x,
                         const float* __restrict__ w4,
                         const float* __restrict__ bng,
                         const float* __restrict__ bnb) {
    __shared__ float2 s[4352];     // FFT phase: 8*SEG=4128; transpose phase: 256*17=4352
    __shared__ float2 s_tw[256];
    int t = threadIdx.x;           // 256
    int w = t >> 5, l = t & 31;
    int bx = blockIdx.x;           // 0..31
    int b  = blockIdx.y;
    int rp = bx * 8 + w;           // row pair (rows 2rp, 2rp+1 of y)

    { float sn, cs; sincospif(-(float)t / 256.0f, &sn, &cs); s_tw[twp(t)] = make_float2(cs, sn); }

    float w0 = w4[0], w1 = w4[1], w2 = w4[2], w3 = w4[3];
    float sc = bng[0] * rsqrtf(1.0f + 1e-5f);
    float bi = bnb[0];

    const float* xr0 = x + (size_t)b * XW * XW + (size_t)(4 * rp) * XW;
    float2* sw = s + w * SEG;
    bool row1ok = (rp < 255);

#pragma unroll
    for (int m = 0; m < 16; m++) {
        int j = l + 32 * m;
        float y0 = 0.0f, y1 = 0.0f;
        if (j < 511) {
            float2 a = *(const float2*)(xr0 + 2 * j);
            float2 c = *(const float2*)(xr0 + XW + 2 * j);
            float z = w0 * a.x + w1 * c.x + w2 * a.y + w3 * c.y;
            z = sc * z + bi;
            y0 = z / (1.0f + expf(-z));
            if (row1ok) {
                float2 a2 = *(const float2*)(xr0 + 2 * (size_t)XW + 2 * j);
                float2 c2 = *(const float2*)(xr0 + 3 * (size_t)XW + 2 * j);
                float z2 = w0 * a2.x + w1 * c2.x + w2 * a2.y + w3 * c2.y;
                z2 = sc * z2 + bi;
                y1 = z2 / (1.0f + expf(-z2));
            }
        }
        sw[sphys(__brev(j) >> 23)] = make_float2(y0, y1);
    }
    __syncthreads();               // also covers s_tw visibility

    fft512_warp(sw, s_tw, l);

    float2 E[8], O[8];
#pragma unroll
    for (int m = 0; m < 8; m++) {
        int k = l + 32 * m;
        float2 Fk = sw[sphys(k)];
        float2 Fn = sw[sphys((NP - k) & (NP - 1))];
        E[m] = make_float2(0.5f * (Fk.x + Fn.x), 0.5f * (Fk.y - Fn.y));
        float2 D = make_float2(0.5f * (Fk.x - Fn.x), 0.5f * (Fk.y + Fn.y));
        O[m] = make_float2(D.y, -D.x);
    }
    __syncthreads();

#pragma unroll
    for (int m = 0; m < 8; m++) {
        int k = l + 32 * m;
        s[k * 17 + 2 * w]     = E[m];
        s[k * 17 + 2 * w + 1] = O[m];
    }
    __syncthreads();

    float2* F1b = g_F1 + (size_t)b * HH * NP + 16 * bx;
#pragma unroll
    for (int it = 0; it < 16; it++) {
        int i  = t + 256 * it;
        int k  = i >> 4, rr = i & 15;
        F1b[(size_t)k * NP + rr] = s[k * 17 + rr];
    }
}

// ---------------------------------------------------------------------------
// Kernel 2: column FFT (one column per warp, coalesced 4KB column reads),
// split-write into the 4 planes.
__global__ void k_colfft() {
    __shared__ float2 s[8 * SEG];
    __shared__ float2 s_tw[256];
    int t = threadIdx.x;           // 256
    int w = t >> 5, l = t & 31;
    int bx = blockIdx.x;           // 0..31
    int b  = blockIdx.y;
    int k  = bx * 8 + w;

    { float sn, cs; sincospif(-(float)t / 256.0f, &sn, &cs); s_tw[twp(t)] = make_float2(cs, sn); }
    __syncthreads();

    const float2* col = g_F1 + ((size_t)b * HH + k) * NP;
    float2* sw = s + w * SEG;
#pragma unroll
    for (int m = 0; m < 16; m++) {
        int j = l + 32 * m;
        sw[sphys(__brev(j) >> 23)] = col[j];
    }
    __syncwarp();

    fft512_warp(sw, s_tw, l);
    __syncthreads();

    const size_t ps = (size_t)NB * HH * HH;
    int k0 = bx * 8;
#pragma unroll
    for (int it = 0; it < 16; it++) {
        int i = t + 256 * it;
        int n = i >> 3, c = i & 7;
        float2 v = s[c * SEG + sphys(n)];
        int kk = k0 + c;
        if (n < HH) {
            size_t o = ((size_t)b * HH + n) * HH + kk;
            g_planes[o]      = v.x;
            g_planes[ps + o] = v.y;
        } else {
            size_t o = ((size_t)b * HH + (n - HH)) * HH + kk;
            g_planes[2 * ps + o] = v.x;
            g_planes[3 * ps + o] = v.y;
        }
    }
}

// ---------------------------------------------------------------------------
// Kernel 3: per-(plane,pixel) 3x3 conv + bias and cumprod over batch in a
// register. One thread per (plane, pixel).
__global__ void k_sdi(const float* __restrict__ sw9, const float* __restrict__ sb) {
    __shared__ float s_w[9];
    int t = threadIdx.x;           // 256
    if (t < 9) s_w[t] = sw9[t];
    __syncthreads();

    int p = blockIdx.y;            // plane
    int i = blockIdx.x;            // row
    int j = t;                     // col
    float sdib = sb[0];

    const size_t ps = (size_t)NB * HH * HH;
    const float* P = g_planes + (size_t)p * ps;
    float* C = g_cp + (size_t)p * ps + (size_t)i * HH + j;

    float pr = 1.0f;
    for (int b = 0; b < NB; b++) {
        const float* Pb = P + (size_t)b * HH * HH;
        float c = sdib;
#pragma unroll
        for (int dr = 0; dr < 3; dr++) {
            int ri = i + dr - 1;
            if ((unsigned)ri < (unsigned)HH) {
                const float* row = Pb + (size_t)ri * HH;
#pragma unroll
                for (int dc = 0; dc < 3; dc++) {
                    int cj = j + dc - 1;
                    float q = ((unsigned)cj < (unsigned)HH) ? __ldg(row + cj) : 0.0f;
                    c = fmaf(s_w[dr * 3 + dc], q, c);
                }
            }
        }
        pr *= c;
        C[(size_t)b * HH * HH] = pr;
    }
}

// ---------------------------------------------------------------------------
// Kernel 4: fuse 4 cumprod planes + BN+SiLU + BN+ReLU + broadcast by w_final
// into out (16,64,256,256). 4096 blocks, o-loop split 4 ways, streaming stores.
__global__ void k_bcast(const float* __restrict__ fw,  const float* __restrict__ fg,
                        const float* __restrict__ fb,  const float* __restrict__ gg,
                        const float* __restrict__ gb,  const float* __restrict__ wf,
                        float* __restrict__ out) {
    __shared__ float swf[64];
    int t = threadIdx.x;           // 256
    if (t < 64) swf[t] = wf[t];
    __syncthreads();

    int b  = blockIdx.y;
    int r  = blockIdx.x;           // row 0..255
    int og = t >> 6;               // o-group 0..3 (16 o's each)
    int c4 = t & 63;               // float4 lane within row

    float fsc = fg[0] * rsqrtf(1.0f + 1e-5f);
    float fbi = fb[0];
    float gsc = gg[0] * rsqrtf(1.0f + 1e-5f);
    float gbi = gb[0];
    float fw0 = fw[0], fw1 = fw[1], fw2 = fw[2], fw3 = fw[3];

    const size_t ps = (size_t)NB * HH * HH;
    size_t off = ((size_t)b * HH + r) * HH + 4 * c4;
    float4 a0 = *(const float4*)(g_cp + off);
    float4 a1 = *(const float4*)(g_cp + ps + off);
    float4 a2 = *(const float4*)(g_cp + 2 * ps + off);
    float4 a3 = *(const float4*)(g_cp + 3 * ps + off);

    float v[4];
#pragma unroll
    for (int e = 0; e < 4; e++) {
        float acc = fw0 * ((const float*)&a0)[e]
                  + fw1 * ((const float*)&a1)[e]
                  + fw2 * ((const float*)&a2)[e]
                  + fw3 * ((const float*)&a3)[e];
        float u = fsc * acc + fbi;
        u = u / (1.0f + expf(-u));
        v[e] = fmaxf(gsc * u + gbi, 0.0f);
    }

    float* ob = out + ((((size_t)b * 64 + og * 16) * HH + r) * HH + 4 * c4);
#pragma unroll
    for (int oo = 0; oo < 16; oo++) {
        float wv = swf[og * 16 + oo];
        __stcs((float4*)(ob + (size_t)oo * HH * HH),
               make_float4(wv * v[0], wv * v[1], wv * v[2], wv * v[3]));
    }
}

// ---------------------------------------------------------------------------
extern "C" void kernel_launch(void* const* d_in, const int* in_sizes, int n_in,
                              void* d_out, int out_size) {
    const float* x       = (const float*)d_in[0];
    // gw branch (indices 1..8) is dead: softmax over the singleton K*K axis == 1.
    const float* w_spd   = (const float*)d_in[9];
    const float* bn_g    = (const float*)d_in[10];
    const float* bn_b    = (const float*)d_in[11];
    const float* sdi_w   = (const float*)d_in[12];
    const float* sdi_b   = (const float*)d_in[13];
    const float* fuse_w  = (const float*)d_in[14];
    const float* fuse_g  = (const float*)d_in[15];
    const float* fuse_b  = (const float*)d_in[16];
    const float* gen_g   = (const float*)d_in[17];
    const float* gen_b   = (const float*)d_in[18];
    const float* w_final = (const float*)d_in[19];
    float* out = (float*)d_out;

    dim3 g1(32, NB);
    k_rowfft<<<g1, 256>>>(x, w_spd, bn_g, bn_b);

    dim3 g2(32, NB);
    k_colfft<<<g2, 256>>>();

    dim3 g3(HH, 4);
    k_sdi<<<g3, 256>>>(sdi_w, sdi_b);

    dim3 g4(HH, NB);
    k_bcast<<<g4, 256>>>(fuse_w, fuse_g, fuse_b, gen_g, gen_b, w_final, out);
}